// round 9
// baseline (speedup 1.0000x reference)
#include <cuda_runtime.h>

#define NN 100000
#define EE 800000
#define DD 64
#define TOT (EE + NN)
#define ROUNDS 4
#define SCAN_B ((NN + 1023) / 1024)   // 98 blocks
#define XT_STR 260                     // XsT row stride (floats): 16B-aligned
#define GEMM_ROWS 256                  // rows per block tile
#define GEMM_SMEM ((64 * XT_STR + 64 * 128) * 4)   // 66560 + 32768 = 99328 B

// ---------------- scratch (device globals: no runtime allocation) ----------
__device__ float g_h[NN * DD];     // gemm out (fp32) / agg gather input
__device__ float g_xa[NN * DD];    // round ping buffer
__device__ int   g_rowptr[NN];     // block-local exclusive prefix of degree
__device__ int   g_cur[NN];        // edge count per dst (excl self-loop)
__device__ int   g_cnt2[NN];       // fill cursor
__device__ float g_dis[NN];        // deg^-1/2
__device__ int2  g_edge[TOT];      // CSR-by-dst: {src, bitcast(norm)}
__device__ int   g_bsum[128];
__device__ int   g_boff[128];
__device__ int   g_done;

#define FFMA2(acc, a, b) \
    asm("fma.rn.f32x2 %0, %1, %2, %0;" : "+l"(acc) : "l"(a), "l"(b))

// ---------------- helpers ---------------------------------------------------
__device__ __forceinline__ int warp_incl_scan(int x) {
    int lane = threadIdx.x & 31;
#pragma unroll
    for (int o = 1; o < 32; o <<= 1) {
        int t = __shfl_up_sync(0xffffffffu, x, o);
        if (lane >= o) x += t;
    }
    return x;
}

// ---------------- CSR build -------------------------------------------------
__global__ void k_zero() {
    int i = blockIdx.x * 256 + threadIdx.x;
    if (i < NN) { g_cur[i] = 0; g_cnt2[i] = 0; }
    if (i == 0) g_done = 0;
}

__global__ void k_count(const int* __restrict__ ei) {
    int e = blockIdx.x * 256 + threadIdx.x;
    if (e < EE) atomicAdd(&g_cur[ei[EE + e]], 1);  // dst row of edge_index
}

// Per-block exclusive scan of degree (+self-loop), dis = rsqrt(deg);
// last-arriving block scans the 98 block sums into g_boff.
__global__ void k_scan() {  // grid = SCAN_B, block 1024
    __shared__ int ws[32];
    __shared__ int ws2[4];
    __shared__ int isLast;
    int i = blockIdx.x * 1024 + threadIdx.x;
    int lane = threadIdx.x & 31, wid = threadIdx.x >> 5;

    int deg = (i < NN) ? (g_cur[i] + 1) : 0;   // +1 self loop
    if (i < NN) g_dis[i] = rsqrtf((float)deg);

    int inc = warp_incl_scan(deg);
    if (lane == 31) ws[wid] = inc;
    __syncthreads();
    if (wid == 0) {
        int s = ws[lane];
        s = warp_incl_scan(s);
        ws[lane] = s;
    }
    __syncthreads();
    int base = wid ? ws[wid - 1] : 0;
    if (i < NN) g_rowptr[i] = base + inc - deg;  // exclusive, block-local

    if (threadIdx.x == 1023) {
        g_bsum[blockIdx.x] = base + inc;
        __threadfence();
        int t = atomicAdd(&g_done, 1);
        isLast = (t == (int)gridDim.x - 1);
    }
    __syncthreads();

    if (isLast) {
        int tid = threadIdx.x;
        int v = 0, inc2 = 0;
        if (tid < 128) {
            v = (tid < (int)gridDim.x) ? g_bsum[tid] : 0;
            inc2 = warp_incl_scan(v);
            if ((tid & 31) == 31) ws2[tid >> 5] = inc2;
        }
        __syncthreads();
        if (tid == 0) {
            int a = ws2[0], b = ws2[1], c = ws2[2];
            ws2[0] = 0; ws2[1] = a; ws2[2] = a + b; ws2[3] = a + b + c;
        }
        __syncthreads();
        if (tid < 128 && tid < (int)gridDim.x)
            g_boff[tid] = ws2[tid >> 5] + inc2 - v;  // exclusive across blocks
    }
}

__global__ void k_fill(const int* __restrict__ ei) {
    int t = blockIdx.x * 256 + threadIdx.x;
    if (t >= TOT) return;
    int s, d;
    if (t < EE) { s = ei[t]; d = ei[EE + t]; }
    else        { s = d = t - EE; }                 // self loop
    int r = atomicAdd(&g_cnt2[d], 1);
    int pos = g_rowptr[d] + g_boff[d >> 10] + r;
    float nrm = g_dis[s] * g_dis[d];
    g_edge[pos] = make_int2(s, __float_as_int(nrm));  // single 8B store
}

// ---------------- GEMM: H[N,64] = X[N,64] @ W[64,64], fp32 FFMA2 -----------
// 256 threads, 256-row tile. Micro-tile: 8 rows (4 row-pairs) x 8 cols.
//   tr = tid>>3: rows tr*8..tr*8+7.   tc = tid&7: cols 8*tc..8*tc+7.
// XsT: transposed X (k-major) -> x row-pairs native via LDS.128 (no splat).
// Wsp: W pre-splatted (w,w) pairs -> W operand native via LDS.128 (no splat).
// Inner loop per k: 2+4 LDS.128 + 32 FFMA2. Delivery 24 cyc vs fma 16 cyc
// per warp-k (smem-delivery bound, floor ~18us/round).
__global__ void __launch_bounds__(256, 2) k_gemm(const float* __restrict__ Xext,
                                                 int in_sel,
                                                 const float* __restrict__ Wg) {
    extern __shared__ __align__(16) float smem[];
    float* XsT = smem;                 // [64][XT_STR]: x[row][k] at [k*XT_STR+row]
    float* Wsp = smem + 64 * XT_STR;   // [64][128]: (W[k][c],W[k][c]) at [k*128+2c]
    int tid = threadIdx.x;

    const float* X = (in_sel == 0) ? Xext : g_xa;
    int row0 = blockIdx.x * GEMM_ROWS;

    // --- prologue: splat W into smem ---
#pragma unroll
    for (int j = 0; j < 4; j++) {
        int f = tid + j * 256;              // float4 index into W (64x64)
        int k = f >> 4, c4 = f & 15;
        float4 v = ((const float4*)Wg)[f];
        float* dst = &Wsp[k * 128 + c4 * 8];
        *(float2*)(dst + 0) = make_float2(v.x, v.x);
        *(float2*)(dst + 2) = make_float2(v.y, v.y);
        *(float2*)(dst + 4) = make_float2(v.z, v.z);
        *(float2*)(dst + 6) = make_float2(v.w, v.w);
    }

    // --- prologue: transposed X tile (row-fastest: lanes hit consecutive
    // rows -> transposed STS.32 consecutive banks, conflict-free) ---
#pragma unroll
    for (int j = 0; j < 16; j++) {
        int t = tid + j * 256;              // 0..4095
        int c4 = t >> 8, r = t & 255;       // c4: float4 within row, r: row
        float4 v;
        if (row0 + r < NN) v = ((const float4*)X)[(size_t)(row0 + r) * 16 + c4];
        else v = make_float4(0.f, 0.f, 0.f, 0.f);
        XsT[(c4 * 4 + 0) * XT_STR + r] = v.x;
        XsT[(c4 * 4 + 1) * XT_STR + r] = v.y;
        XsT[(c4 * 4 + 2) * XT_STR + r] = v.z;
        XsT[(c4 * 4 + 3) * XT_STR + r] = v.w;
    }
    __syncthreads();

    int tr = tid >> 3;
    int tc = tid & 7;

    unsigned long long acc[4][8];
#pragma unroll
    for (int rp = 0; rp < 4; rp++)
#pragma unroll
        for (int c = 0; c < 8; c++) acc[rp][c] = 0ull;

#pragma unroll 2
    for (int k = 0; k < 64; k++) {
        // 4 x row-pairs: rows tr*8 .. tr*8+7 via 2 LDS.128
        ulonglong2 xa = *(const ulonglong2*)&XsT[k * XT_STR + tr * 8];
        ulonglong2 xb = *(const ulonglong2*)&XsT[k * XT_STR + tr * 8 + 4];
        unsigned long long xp[4] = {xa.x, xa.y, xb.x, xb.y};
        // 8 splatted W col-pairs (cols 8tc..8tc+7): 4 LDS.128, contiguous 64B
        ulonglong2 w0 = *(const ulonglong2*)&Wsp[k * 128 + 16 * tc + 0];
        ulonglong2 w1 = *(const ulonglong2*)&Wsp[k * 128 + 16 * tc + 4];
        ulonglong2 w2 = *(const ulonglong2*)&Wsp[k * 128 + 16 * tc + 8];
        ulonglong2 w3 = *(const ulonglong2*)&Wsp[k * 128 + 16 * tc + 12];
        unsigned long long wv[8] = {w0.x, w0.y, w1.x, w1.y,
                                    w2.x, w2.y, w3.x, w3.y};
#pragma unroll
        for (int rp = 0; rp < 4; rp++)
#pragma unroll
            for (int c = 0; c < 8; c++)
                FFMA2(acc[rp][c], xp[rp], wv[c]);
    }

    // --- epilogue: acc[rp][c] = (out[r_even][8tc+c], out[r_odd][8tc+c]).
    // Per row: 8 contiguous floats -> 2 STG.128 (lanes of same tr: 256B). ---
#pragma unroll
    for (int rp = 0; rp < 4; rp++) {
        int r0 = row0 + tr * 8 + 2 * rp;
        int r1 = r0 + 1;
        float e[8], o[8];
#pragma unroll
        for (int c = 0; c < 8; c++)
            asm("mov.b64 {%0, %1}, %2;" : "=f"(e[c]), "=f"(o[c]) : "l"(acc[rp][c]));
        if (r0 < NN) {
            float4* d0 = (float4*)&g_h[(size_t)r0 * 64 + 8 * tc];
            d0[0] = make_float4(e[0], e[1], e[2], e[3]);
            d0[1] = make_float4(e[4], e[5], e[6], e[7]);
        }
        if (r1 < NN) {
            float4* d1 = (float4*)&g_h[(size_t)r1 * 64 + 8 * tc];
            d1[0] = make_float4(o[0], o[1], o[2], o[3]);
            d1[1] = make_float4(o[4], o[5], o[6], o[7]);
        }
    }
}

// ---------------- fused gather-aggregate + bias + LayerNorm -----------------
// One warp per destination node; lane owns features {2*lane, 2*lane+1}.
// out_sel: 0 = g_xa, 1 = external out.
__global__ void __launch_bounds__(256) k_agg(const float* __restrict__ bb,
                                             const float* __restrict__ gm,
                                             const float* __restrict__ bt,
                                             float* __restrict__ out_ext,
                                             int out_sel) {
    int w = (blockIdx.x * 256 + threadIdx.x) >> 5;
    int lane = threadIdx.x & 31;
    if (w >= NN) return;

    float* out = (out_sel == 0) ? g_xa : out_ext;

    int s0 = g_rowptr[w] + g_boff[w >> 10];
    int s1 = (w == NN - 1) ? TOT : (g_rowptr[w + 1] + g_boff[(w + 1) >> 10]);

    const float2* h2 = (const float2*)g_h;
    float ax0 = 0.f, ay0 = 0.f, ax1 = 0.f, ay1 = 0.f;
    float ax2 = 0.f, ay2 = 0.f, ax3 = 0.f, ay3 = 0.f;

    int j = s0;
    for (; j + 4 <= s1; j += 4) {
        int2 ea = g_edge[j],     eb = g_edge[j + 1];
        int2 ec = g_edge[j + 2], ed = g_edge[j + 3];
        float2 ha = h2[(size_t)ea.x * 32 + lane];
        float2 hb = h2[(size_t)eb.x * 32 + lane];
        float2 hc = h2[(size_t)ec.x * 32 + lane];
        float2 hd = h2[(size_t)ed.x * 32 + lane];
        float wa = __int_as_float(ea.y), wb = __int_as_float(eb.y);
        float wc = __int_as_float(ec.y), wd = __int_as_float(ed.y);
        ax0 = fmaf(ha.x, wa, ax0); ay0 = fmaf(ha.y, wa, ay0);
        ax1 = fmaf(hb.x, wb, ax1); ay1 = fmaf(hb.y, wb, ay1);
        ax2 = fmaf(hc.x, wc, ax2); ay2 = fmaf(hc.y, wc, ay2);
        ax3 = fmaf(hd.x, wd, ax3); ay3 = fmaf(hd.y, wd, ay3);
    }
    for (; j < s1; j++) {
        int2 e = g_edge[j];
        float2 hv = h2[(size_t)e.x * 32 + lane];
        float wt = __int_as_float(e.y);
        ax0 = fmaf(hv.x, wt, ax0); ay0 = fmaf(hv.y, wt, ay0);
    }
    float ax = (ax0 + ax1) + (ax2 + ax3);
    float ay = (ay0 + ay1) + (ay2 + ay3);

    ax += bb[lane * 2];
    ay += bb[lane * 2 + 1];

    float sum = ax + ay;
    float sq = ax * ax + ay * ay;
#pragma unroll
    for (int o = 16; o; o >>= 1) {
        sum += __shfl_xor_sync(0xffffffffu, sum, o);
        sq  += __shfl_xor_sync(0xffffffffu, sq, o);
    }
    float mu = sum * (1.0f / 64.0f);
    float var = sq * (1.0f / 64.0f) - mu * mu;
    float inv = rsqrtf(var + 1e-5f);

    float2 o2;
    o2.x = (ax - mu) * inv * gm[lane * 2] + bt[lane * 2];
    o2.y = (ay - mu) * inv * gm[lane * 2 + 1] + bt[lane * 2 + 1];
    ((float2*)out)[(size_t)w * 32 + lane] = o2;
}

// ---------------- launch ----------------------------------------------------
extern "C" void kernel_launch(void* const* d_in, const int* in_sizes, int n_in,
                              void* d_out, int out_size) {
    const float* x  = (const float*)d_in[0];
    const int*   ei = (const int*)d_in[1];
    const float* W  = (const float*)d_in[2];
    const float* b  = (const float*)d_in[3];
    const float* gm = (const float*)d_in[4];
    const float* bt = (const float*)d_in[5];
    float* out = (float*)d_out;

    cudaFuncSetAttribute(k_gemm, cudaFuncAttributeMaxDynamicSharedMemorySize,
                         GEMM_SMEM);

    int gemm_grid = (NN + GEMM_ROWS - 1) / GEMM_ROWS;

    k_zero<<<(NN + 255) / 256, 256>>>();
    k_count<<<(EE + 255) / 256, 256>>>(ei);
    k_scan<<<SCAN_B, 1024>>>();
    // gemm round 0 at launch index 3: ncu window captures the NEW gemm config.
    k_gemm<<<gemm_grid, 256, GEMM_SMEM>>>(x, 0, W);
    k_fill<<<(TOT + 255) / 256, 256>>>(ei);
    k_agg<<<(NN * 32 + 255) / 256, 256>>>(b, gm, bt, out, 0);

    for (int r = 1; r < ROUNDS; r++) {
        k_gemm<<<gemm_grid, 256, GEMM_SMEM>>>(x, 1, W);
        k_agg<<<(NN * 32 + 255) / 256, 256>>>(b, gm, bt, out, r == 3 ? 1 : 0);
    }
}

// round 10
// speedup vs baseline: 1.6740x; 1.6740x over previous
#include <cuda_runtime.h>

#define NN 100000
#define EE 800000
#define DD 64
#define TOT (EE + NN)
#define ROUNDS 4
#define SCAN_B ((NN + 1023) / 1024)   // 98 blocks

// ---------------- scratch (device globals: no runtime allocation) ----------
__device__ float g_h[NN * DD];     // gemm out (fp32) / agg gather input
__device__ float g_xa[NN * DD];    // round ping buffer
__device__ int   g_rowptr[NN];     // block-local exclusive prefix of degree
__device__ int   g_cur[NN];        // edge count per dst (excl self-loop)
__device__ int   g_cnt2[NN];       // fill cursor
__device__ float g_dis[NN];        // deg^-1/2
__device__ int2  g_edge[TOT];      // CSR-by-dst: {src, bitcast(norm)}
__device__ int   g_bsum[128];
__device__ int   g_boff[128];
__device__ int   g_done;

// ---------------- helpers ---------------------------------------------------
__device__ __forceinline__ int warp_incl_scan(int x) {
    int lane = threadIdx.x & 31;
#pragma unroll
    for (int o = 1; o < 32; o <<= 1) {
        int t = __shfl_up_sync(0xffffffffu, x, o);
        if (lane >= o) x += t;
    }
    return x;
}

// ---------------- CSR build -------------------------------------------------
__global__ void k_zero() {
    int i = blockIdx.x * 256 + threadIdx.x;
    if (i < NN) { g_cur[i] = 0; g_cnt2[i] = 0; }
    if (i == 0) g_done = 0;
}

__global__ void k_count(const int* __restrict__ ei) {
    int e = blockIdx.x * 256 + threadIdx.x;
    if (e < EE) atomicAdd(&g_cur[ei[EE + e]], 1);  // dst row of edge_index
}

// Per-block exclusive scan of degree (+self-loop), dis = rsqrt(deg);
// last-arriving block scans the 98 block sums into g_boff.
__global__ void k_scan() {  // grid = SCAN_B, block 1024
    __shared__ int ws[32];
    __shared__ int ws2[4];
    __shared__ int isLast;
    int i = blockIdx.x * 1024 + threadIdx.x;
    int lane = threadIdx.x & 31, wid = threadIdx.x >> 5;

    int deg = (i < NN) ? (g_cur[i] + 1) : 0;   // +1 self loop
    if (i < NN) g_dis[i] = rsqrtf((float)deg);

    int inc = warp_incl_scan(deg);
    if (lane == 31) ws[wid] = inc;
    __syncthreads();
    if (wid == 0) {
        int s = ws[lane];
        s = warp_incl_scan(s);
        ws[lane] = s;
    }
    __syncthreads();
    int base = wid ? ws[wid - 1] : 0;
    if (i < NN) g_rowptr[i] = base + inc - deg;  // exclusive, block-local

    if (threadIdx.x == 1023) {
        g_bsum[blockIdx.x] = base + inc;
        __threadfence();
        int t = atomicAdd(&g_done, 1);
        isLast = (t == (int)gridDim.x - 1);
    }
    __syncthreads();

    if (isLast) {
        int tid = threadIdx.x;
        int v = 0, inc2 = 0;
        if (tid < 128) {
            v = (tid < (int)gridDim.x) ? g_bsum[tid] : 0;
            inc2 = warp_incl_scan(v);
            if ((tid & 31) == 31) ws2[tid >> 5] = inc2;
        }
        __syncthreads();
        if (tid == 0) {
            int a = ws2[0], b = ws2[1], c = ws2[2];
            ws2[0] = 0; ws2[1] = a; ws2[2] = a + b; ws2[3] = a + b + c;
        }
        __syncthreads();
        if (tid < 128 && tid < (int)gridDim.x)
            g_boff[tid] = ws2[tid >> 5] + inc2 - v;  // exclusive across blocks
    }
}

__global__ void k_fill(const int* __restrict__ ei) {
    int t = blockIdx.x * 256 + threadIdx.x;
    if (t >= TOT) return;
    int s, d;
    if (t < EE) { s = ei[t]; d = ei[EE + t]; }
    else        { s = d = t - EE; }                 // self loop
    int r = atomicAdd(&g_cnt2[d], 1);
    int pos = g_rowptr[d] + g_boff[d >> 10] + r;
    float nrm = g_dis[s] * g_dis[d];
    g_edge[pos] = make_int2(s, __float_as_int(nrm));  // single 8B store
}

// ---------------- GEMM: H[N,64] = X[N,64] @ W[64,64], fp32 FFMA2 -----------
// EXACT R5 configuration (measured 27.0us) with fp32 output.
// 256 threads/block, 128-row tile. Micro-tile: 4 rows x 4 col-pairs.
// tr = tid>>3 (rows tr*4..tr*4+3), tc = tid&7 (pairs tc,tc+8,tc+16,tc+24).
// in_sel: 0 = external x, 1 = g_xa. Output always g_h (fp32).
__global__ void __launch_bounds__(256) k_gemm(const float* __restrict__ Xext,
                                              int in_sel,
                                              const float* __restrict__ Wg) {
    __shared__ __align__(16) float Ws[64 * 64];
    __shared__ __align__(16) float Xs[128 * 65];  // stride 65: conflict-free
    int tid = threadIdx.x;

    const float* X = (in_sel == 0) ? Xext : g_xa;

    const float4* W4 = (const float4*)Wg;
    float4* Ws4 = (float4*)Ws;
#pragma unroll
    for (int i = tid; i < 1024; i += 256) Ws4[i] = W4[i];

    int row0 = blockIdx.x * 128;
#pragma unroll
    for (int t = tid; t < 2048; t += 256) {
        int r = t >> 4, c4 = t & 15;
        float4 v;
        if (row0 + r < NN) v = ((const float4*)X)[(size_t)(row0 + r) * 16 + c4];
        else v = make_float4(0.f, 0.f, 0.f, 0.f);
        float* p = &Xs[r * 65 + c4 * 4];
        p[0] = v.x; p[1] = v.y; p[2] = v.z; p[3] = v.w;
    }
    __syncthreads();

    int tr = tid >> 3;  // rows tr*4 .. tr*4+3
    int tc = tid & 7;   // col pairs {tc, tc+8, tc+16, tc+24}

    unsigned long long acc[4][4];
#pragma unroll
    for (int r = 0; r < 4; r++)
#pragma unroll
        for (int c = 0; c < 4; c++) acc[r][c] = 0ull;

#pragma unroll 4
    for (int k = 0; k < 64; k++) {
        unsigned long long wv[4];
#pragma unroll
        for (int c = 0; c < 4; c++)
            wv[c] = *(const unsigned long long*)&Ws[k * 64 + 2 * (tc + 8 * c)];
        unsigned long long xp[4];
#pragma unroll
        for (int r = 0; r < 4; r++) {
            unsigned u = __float_as_uint(Xs[(tr * 4 + r) * 65 + k]);
            asm("mov.b64 %0, {%1, %1};" : "=l"(xp[r]) : "r"(u));
        }
#pragma unroll
        for (int r = 0; r < 4; r++)
#pragma unroll
            for (int c = 0; c < 4; c++)
                asm("fma.rn.f32x2 %0, %1, %2, %0;"
                    : "+l"(acc[r][c]) : "l"(xp[r]), "l"(wv[c]));
    }

    float2* Hp = (float2*)g_h;
#pragma unroll
    for (int r = 0; r < 4; r++) {
        int row = row0 + tr * 4 + r;
        if (row < NN) {
#pragma unroll
            for (int c = 0; c < 4; c++) {
                float2 v;
                asm("mov.b64 {%0, %1}, %2;" : "=f"(v.x), "=f"(v.y) : "l"(acc[r][c]));
                Hp[(size_t)row * 32 + tc + 8 * c] = v;
            }
        }
    }
}

// ---------------- fused gather-aggregate + bias + LayerNorm -----------------
// One warp per destination node; lane owns features {2*lane, 2*lane+1}.
// out_sel: 0 = g_xa, 1 = external out.
__global__ void __launch_bounds__(256) k_agg(const float* __restrict__ bb,
                                             const float* __restrict__ gm,
                                             const float* __restrict__ bt,
                                             float* __restrict__ out_ext,
                                             int out_sel) {
    int w = (blockIdx.x * 256 + threadIdx.x) >> 5;
    int lane = threadIdx.x & 31;
    if (w >= NN) return;

    float* out = (out_sel == 0) ? g_xa : out_ext;

    int s0 = g_rowptr[w] + g_boff[w >> 10];
    int s1 = (w == NN - 1) ? TOT : (g_rowptr[w + 1] + g_boff[(w + 1) >> 10]);

    const float2* h2 = (const float2*)g_h;
    float ax0 = 0.f, ay0 = 0.f, ax1 = 0.f, ay1 = 0.f;
    float ax2 = 0.f, ay2 = 0.f, ax3 = 0.f, ay3 = 0.f;

    int j = s0;
    for (; j + 4 <= s1; j += 4) {
        int2 ea = g_edge[j],     eb = g_edge[j + 1];
        int2 ec = g_edge[j + 2], ed = g_edge[j + 3];
        float2 ha = h2[(size_t)ea.x * 32 + lane];
        float2 hb = h2[(size_t)eb.x * 32 + lane];
        float2 hc = h2[(size_t)ec.x * 32 + lane];
        float2 hd = h2[(size_t)ed.x * 32 + lane];
        float wa = __int_as_float(ea.y), wb = __int_as_float(eb.y);
        float wc = __int_as_float(ec.y), wd = __int_as_float(ed.y);
        ax0 = fmaf(ha.x, wa, ax0); ay0 = fmaf(ha.y, wa, ay0);
        ax1 = fmaf(hb.x, wb, ax1); ay1 = fmaf(hb.y, wb, ay1);
        ax2 = fmaf(hc.x, wc, ax2); ay2 = fmaf(hc.y, wc, ay2);
        ax3 = fmaf(hd.x, wd, ax3); ay3 = fmaf(hd.y, wd, ay3);
    }
    for (; j < s1; j++) {
        int2 e = g_edge[j];
        float2 hv = h2[(size_t)e.x * 32 + lane];
        float wt = __int_as_float(e.y);
        ax0 = fmaf(hv.x, wt, ax0); ay0 = fmaf(hv.y, wt, ay0);
    }
    float ax = (ax0 + ax1) + (ax2 + ax3);
    float ay = (ay0 + ay1) + (ay2 + ay3);

    ax += bb[lane * 2];
    ay += bb[lane * 2 + 1];

    float sum = ax + ay;
    float sq = ax * ax + ay * ay;
#pragma unroll
    for (int o = 16; o; o >>= 1) {
        sum += __shfl_xor_sync(0xffffffffu, sum, o);
        sq  += __shfl_xor_sync(0xffffffffu, sq, o);
    }
    float mu = sum * (1.0f / 64.0f);
    float var = sq * (1.0f / 64.0f) - mu * mu;
    float inv = rsqrtf(var + 1e-5f);

    float2 o2;
    o2.x = (ax - mu) * inv * gm[lane * 2] + bt[lane * 2];
    o2.y = (ay - mu) * inv * gm[lane * 2 + 1] + bt[lane * 2 + 1];
    ((float2*)out)[(size_t)w * 32 + lane] = o2;
}

// ---------------- launch ----------------------------------------------------
extern "C" void kernel_launch(void* const* d_in, const int* in_sizes, int n_in,
                              void* d_out, int out_size) {
    const float* x  = (const float*)d_in[0];
    const int*   ei = (const int*)d_in[1];
    const float* W  = (const float*)d_in[2];
    const float* b  = (const float*)d_in[3];
    const float* gm = (const float*)d_in[4];
    const float* bt = (const float*)d_in[5];
    float* out = (float*)d_out;

    k_zero<<<(NN + 255) / 256, 256>>>();
    k_count<<<(EE + 255) / 256, 256>>>(ei);
    k_scan<<<SCAN_B, 1024>>>();
    // gemm round 0 at launch index 3: ncu window captures the reverted gemm.
    k_gemm<<<(NN + 127) / 128, 256>>>(x, 0, W);
    k_fill<<<(TOT + 255) / 256, 256>>>(ei);
    k_agg<<<(NN * 32 + 255) / 256, 256>>>(b, gm, bt, out, 0);

    for (int r = 1; r < ROUNDS; r++) {
        k_gemm<<<(NN + 127) / 128, 256>>>(x, 1, W);
        k_agg<<<(NN * 32 + 255) / 256, 256>>>(b, gm, bt, out, r == 3 ? 1 : 0);
    }
}